// round 9
// baseline (speedup 1.0000x reference)
#include <cuda_runtime.h>
#include <cuda_fp16.h>
#include <cstdint>
#include <cstddef>

typedef __half fp16;

#define T_    4
#define B_    8
#define NSEQ  1024
#define C_    768
#define C3_   2304
#define HD_   3072
#define H_    8
#define D_    96
#define W_    8
#define NW_   (NSEQ / W_)
#define BN_TOK (B_ * NSEQ)
#define M_TOT (T_ * BN_TOK)
#define PLANE_C ((size_t)BN_TOK * C_)
#define MC ((size_t)M_TOT * C_)
#define MH ((size_t)M_TOT * HD_)

#define WOFF_Q  0
#define WOFF_P  1769472
#define WOFF_F1 2359296
#define WOFF_F2 4718592
#define WTOT    7077888

__device__ fp16  g_xs  [2 * MC];
__device__ fp16  g_ws  [2 * WTOT];
__device__ fp16  g_spkf[(size_t)M_TOT * C3_];
__device__ fp16  g_aspk[MC];
__device__ fp16  g_hspk[MH];
__device__ fp16  g_x1s [2 * MC];
__device__ float g_obuf[MC];
__device__ float g_x1  [MC];
__device__ float g_qkvp[3 * C3_];

__device__ __forceinline__ uint32_t smem_u32(const void* p) {
    uint32_t a;
    asm("{ .reg .u64 t; cvta.to.shared.u64 t, %1; cvt.u32.u64 %0, t; }" : "=r"(a) : "l"(p));
    return a;
}
#define SWZ(o) ((o) ^ (((o) >> 3) & 0x70))
__device__ __forceinline__ void cp16cp(uint32_t dst, const void* src) {
    asm volatile("cp.async.cg.shared.global [%0], [%1], 16;" :: "r"(dst), "l"(src));
}
__device__ __forceinline__ void ldm4(uint32_t* a, uint32_t addr) {
    asm volatile("ldmatrix.sync.aligned.m8n8.x4.shared.b16 {%0,%1,%2,%3}, [%4];"
                 : "=r"(a[0]), "=r"(a[1]), "=r"(a[2]), "=r"(a[3]) : "r"(addr));
}
__device__ __forceinline__ void mma16816(float* c, const uint32_t* a, const uint32_t* b) {
    asm volatile(
        "mma.sync.aligned.m16n8k16.row.col.f32.f16.f16.f32 "
        "{%0,%1,%2,%3}, {%4,%5,%6,%7}, {%8,%9}, {%0,%1,%2,%3};"
        : "+f"(c[0]), "+f"(c[1]), "+f"(c[2]), "+f"(c[3])
        : "r"(a[0]), "r"(a[1]), "r"(a[2]), "r"(a[3]), "r"(b[0]), "r"(b[1]));
}
__device__ __forceinline__ void split2f(float x, fp16& h1, fp16& h2) {
    h1 = __float2half_rn(x);
    h2 = __float2half_rn(x - __half2float(h1));
}

// GEMM (fp16 split passes) + BN + fused LIF over t (t looped inside block;
// membrane state lives in per-thread registers mirroring the accumulator cells).
// MODE 0: write fp16 spikes to outS.
// MODE 1: proj: x1 = res + spike -> outF(f32), split2(x1) -> outS/outS2 (fp16).
// MODE 2: f2:   out = res + spike -> outF(f32).
template <int NA, int NSTG, int MODE>
__global__ __launch_bounds__(256, 1)
void gemm_lif(const fp16* __restrict__ A0, const fp16* __restrict__ A1,
              const fp16* __restrict__ B0, const fp16* __restrict__ B1,
              const float* __restrict__ bia, const float* __restrict__ sca,
              const float* __restrict__ shf, const float* __restrict__ res,
              float* __restrict__ outF, fp16* __restrict__ outS, fp16* __restrict__ outS2,
              int N, int K)
{
    extern __shared__ char smem[];
    const uint32_t sb = smem_u32(smem);
    const uint32_t tiles = (sb + 1023u) & ~1023u;
    constexpr int NT = NA + 2;
    constexpr uint32_t STAGE = NT * 16384u;

    const int bm = blockIdx.y * 128;
    const int bn = blockIdx.x * 128;
    const int tid = threadIdx.x;
    const int wid = tid >> 5, lane = tid & 31;
    const int wm0 = (wid >> 2) * 64;
    const int wn0 = (wid & 3) * 32;

    const fp16* Aps[2] = {A0, A1};
    const fp16* Bps[2] = {B0, B1};
    const int NC = K >> 6;
    const int TOT = 4 * NC;

    auto issue_loads = [&](int g) {
        const int tt = g / NC, ch = g - tt * NC;
        const uint32_t base = tiles + (uint32_t)(g % NSTG) * STAGE;
        const int k0 = ch << 6;
        #pragma unroll
        for (int a = 0; a < NA; a++) {
            const fp16* src = Aps[a] + (size_t)(tt * BN_TOK + bm) * K + k0;
            const uint32_t tb = base + a * 16384u;
            #pragma unroll
            for (int j = 0; j < 4; j++) {
                int idx = tid + j * 256;
                int row = idx >> 3, c = idx & 7;
                cp16cp(tb + SWZ((uint32_t)(row * 128 + c * 16)), src + (size_t)row * K + c * 8);
            }
        }
        #pragma unroll
        for (int b = 0; b < 2; b++) {
            const fp16* src = Bps[b] + (size_t)bn * K + k0;
            const uint32_t tb = base + (NA + b) * 16384u;
            #pragma unroll
            for (int j = 0; j < 4; j++) {
                int idx = tid + j * 256;
                int row = idx >> 3, c = idx & 7;
                cp16cp(tb + SWZ((uint32_t)(row * 128 + c * 16)), src + (size_t)row * K + c * 8);
            }
        }
        asm volatile("cp.async.commit_group;" ::: "memory");
    };

    // BN params per owned columns (fixed across t): y = acc*sc + of
    const int crow = lane >> 2, ccol = (lane & 3) * 2;
    float scv[4][2], ofv[4][2];
    #pragma unroll
    for (int na = 0; na < 4; na++) {
        #pragma unroll
        for (int e = 0; e < 2; e++) {
            const int cg = bn + wn0 + na * 8 + ccol + e;
            const float s_ = sca[cg];
            scv[na][e] = s_;
            ofv[na][e] = bia[cg] * s_ + shf[cg];
        }
    }

    float acc[4][4][4];
    float vmem[4][4][4];
    #pragma unroll
    for (int i = 0; i < 4; i++)
        #pragma unroll
        for (int j = 0; j < 4; j++)
            #pragma unroll
            for (int e = 0; e < 4; e++) { acc[i][j][e] = 0.f; vmem[i][j][e] = 0.f; }

    #pragma unroll
    for (int p = 0; p < NSTG - 1; p++)
        if (p < TOT) issue_loads(p);

    const int arow = lane & 15, akg = lane >> 4;
    const int brow = lane & 7, bkh = (lane >> 3) & 1, batm = lane >> 4;

    for (int g = 0; g < TOT; g++) {
        const int t = g / NC, chunk = g - t * NC;
        if (g + NSTG - 1 < TOT) {
            issue_loads(g + NSTG - 1);
            asm volatile("cp.async.wait_group %0;" :: "n"(NSTG - 1) : "memory");
        } else {
            asm volatile("cp.async.wait_group 0;" ::: "memory");
        }
        __syncthreads();
        const uint32_t base = tiles + (uint32_t)(g % NSTG) * STAGE;

        #pragma unroll
        for (int s = 0; s < 4; s++) {
            const int kb = s * 32;
            uint32_t af[NA][4][4];
            #pragma unroll
            for (int ai = 0; ai < NA; ai++)
                #pragma unroll
                for (int ma = 0; ma < 4; ma++)
                    ldm4(af[ai][ma], base + ai * 16384u +
                         SWZ((uint32_t)((wm0 + ma * 16 + arow) * 128 + kb + akg * 16)));
            uint32_t bfr[2][4][2];
            #pragma unroll
            for (int bi = 0; bi < 2; bi++)
                #pragma unroll
                for (int pr = 0; pr < 2; pr++) {
                    uint32_t r[4];
                    ldm4(r, base + (NA + bi) * 16384u +
                         SWZ((uint32_t)((wn0 + pr * 16 + batm * 8 + brow) * 128 + kb + bkh * 16)));
                    bfr[bi][pr * 2][0] = r[0]; bfr[bi][pr * 2][1] = r[1];
                    bfr[bi][pr * 2 + 1][0] = r[2]; bfr[bi][pr * 2 + 1][1] = r[3];
                }
            #pragma unroll
            for (int ai = 0; ai < NA; ai++)
                #pragma unroll
                for (int bi = 0; bi < 2; bi++)
                    #pragma unroll
                    for (int ma = 0; ma < 4; ma++)
                        #pragma unroll
                        for (int na = 0; na < 4; na++)
                            mma16816(acc[ma][na], af[ai][ma], bfr[bi][na]);
        }
        __syncthreads();

        if (chunk == NC - 1) {
            // fused BN + LIF epilogue for this t (all state thread-private)
            #pragma unroll
            for (int ma = 0; ma < 4; ma++) {
                #pragma unroll
                for (int half = 0; half < 2; half++) {
                    const int r = wm0 + ma * 16 + crow + half * 8;
                    const size_t rowg = (size_t)(t * BN_TOK + bm + r);
                    #pragma unroll
                    for (int na = 0; na < 4; na++) {
                        const int cg = bn + wn0 + na * 8 + ccol;
                        const float y0 = acc[ma][na][half * 2]     * scv[na][0] + ofv[na][0];
                        const float y1 = acc[ma][na][half * 2 + 1] * scv[na][1] + ofv[na][1];
                        float v0 = vmem[ma][na][half * 2];
                        float v1 = vmem[ma][na][half * 2 + 1];
                        v0 = v0 + (y0 - v0) * 0.5f;
                        v1 = v1 + (y1 - v1) * 0.5f;
                        const bool s0 = (v0 >= 1.f), s1 = (v1 >= 1.f);
                        if (s0) v0 = 0.f;
                        if (s1) v1 = 0.f;
                        vmem[ma][na][half * 2]     = v0;
                        vmem[ma][na][half * 2 + 1] = v1;
                        const float f0 = s0 ? 1.f : 0.f, f1 = s1 ? 1.f : 0.f;
                        if (MODE == 0) {
                            *(__half2*)(outS + rowg * N + cg) =
                                __halves2half2(__float2half_rn(f0), __float2half_rn(f1));
                        } else if (MODE == 1) {
                            const float2 xr = *(const float2*)(res + rowg * N + cg);
                            const float o0 = xr.x + f0, o1 = xr.y + f1;
                            float2 ov; ov.x = o0; ov.y = o1;
                            *(float2*)(outF + rowg * N + cg) = ov;
                            fp16 h0a, h0b, h1a, h1b;
                            split2f(o0, h0a, h0b);
                            split2f(o1, h1a, h1b);
                            *(__half2*)(outS + rowg * N + cg)  = __halves2half2(h0a, h1a);
                            *(__half2*)(outS2 + rowg * N + cg) = __halves2half2(h0b, h1b);
                        } else {
                            const float2 xr = *(const float2*)(res + rowg * N + cg);
                            float2 ov; ov.x = xr.x + f0; ov.y = xr.y + f1;
                            *(float2*)(outF + rowg * N + cg) = ov;
                        }
                        acc[ma][na][half * 2] = 0.f;
                        acc[ma][na][half * 2 + 1] = 0.f;
                    }
                }
            }
        }
    }
}

__global__ void split2_kernel(const float2* __restrict__ src, __half2* __restrict__ a,
                              __half2* __restrict__ b, size_t n2)
{
    size_t i = (size_t)blockIdx.x * blockDim.x + threadIdx.x;
    if (i >= n2) return;
    float2 x = src[i];
    fp16 a0, b0, a1, b1;
    split2f(x.x, a0, b0);
    split2f(x.y, a1, b1);
    a[i] = __halves2half2(a0, a1);
    b[i] = __halves2half2(b0, b1);
}

__global__ void concat3_kernel(const float* __restrict__ a, const float* __restrict__ b,
                               const float* __restrict__ c, float* __restrict__ dst)
{
    int i = blockIdx.x * blockDim.x + threadIdx.x;
    if (i >= C3_) return;
    dst[i] = (i < C_) ? a[i] : (i < 2 * C_) ? b[i - C_] : c[i - 2 * C_];
}

// attn_lif (vth=0.5): f32 attention output -> fp16 spikes
__global__ void lif_spk_kernel(const float2* __restrict__ pre, __half2* __restrict__ spk,
                               size_t plane2, float vth)
{
    size_t i = (size_t)blockIdx.x * blockDim.x + threadIdx.x;
    if (i >= plane2) return;
    float v0 = 0.f, v1 = 0.f;
    const fp16 one = __float2half_rn(1.0f), zero = __float2half_rn(0.0f);
    #pragma unroll
    for (int t = 0; t < T_; t++) {
        float2 x = pre[(size_t)t * plane2 + i];
        v0 = v0 + (x.x - v0) * 0.5f; bool s0 = (v0 >= vth); if (s0) v0 = 0.f;
        v1 = v1 + (x.y - v1) * 0.5f; bool s1 = (v1 >= vth); if (s1) v1 = 0.f;
        spk[(size_t)t * plane2 + i] = __halves2half2(s0 ? one : zero, s1 ? one : zero);
    }
}

// local attention over fused spike tensor [T][B*N][2304]: q@0, k@768, v@1536
__global__ void attn_kernel(const fp16* __restrict__ sf, float* __restrict__ og)
{
    __shared__ float Qs[8][97];
    __shared__ float Ks[16][97];
    __shared__ float Vs[16][97];
    __shared__ float At[8][16];

    const int nwi = blockIdx.x, b = blockIdx.y, t = blockIdx.z;
    const int tid = threadIdx.x;
    const size_t basef = ((size_t)t * B_ + b) * (size_t)NSEQ * C3_;
    const size_t baseo = ((size_t)t * B_ + b) * (size_t)NSEQ * C_;
    const int n0 = nwi * W_;
    const float scale = 0.10206207261596577f;

    for (int h = 0; h < H_; h++) {
        const int c0 = h * D_;
        for (int r = tid; r < 8 * 96; r += 128) {
            int i = r / 96, d = r - i * 96;
            Qs[i][d] = __half2float(sf[basef + (size_t)(n0 + i) * C3_ + c0 + d]);
        }
        for (int r = tid; r < 16 * 96; r += 128) {
            int j = r / 96, d = r - j * 96;
            int n = n0 - 8 + j;
            float kv = 0.f, vv = 0.f;
            if (n >= 0) {
                size_t off = basef + (size_t)n * C3_ + c0 + d;
                kv = __half2float(sf[off + C_]);
                vv = __half2float(sf[off + 2 * C_]);
            }
            Ks[j][d] = kv; Vs[j][d] = vv;
        }
        __syncthreads();

        const int i = tid >> 4, j = tid & 15;
        float acc = 0.f;
        #pragma unroll
        for (int d = 0; d < 96; d++) acc += Qs[i][d] * Ks[j][d];
        float sim = acc * scale;
        if (nwi == 0 && j < 8) sim = -3.0e38f;

        float mx = sim;
        #pragma unroll
        for (int off = 8; off > 0; off >>= 1)
            mx = fmaxf(mx, __shfl_xor_sync(0xffffffffu, mx, off));
        float e = expf(sim - mx);
        float ssum = e;
        #pragma unroll
        for (int off = 8; off > 0; off >>= 1)
            ssum += __shfl_xor_sync(0xffffffffu, ssum, off);
        At[i][j] = e / ssum;
        __syncthreads();

        for (int r = tid; r < 8 * 96; r += 128) {
            int ii = r / 96, d = r - ii * 96;
            float o = 0.f;
            #pragma unroll
            for (int jj = 0; jj < 16; jj++) o += At[ii][jj] * Vs[jj][d];
            og[baseo + (size_t)(n0 + ii) * C_ + c0 + d] = o;
        }
        __syncthreads();
    }
}

extern "C" void kernel_launch(void* const* d_in, const int* in_sizes, int n_in,
                              void* d_out, int out_size)
{
    const float* x   = (const float*)d_in[0];
    const float* qw  = (const float*)d_in[1];
    const float* qb  = (const float*)d_in[2];
    const float* qs  = (const float*)d_in[3];
    const float* qt  = (const float*)d_in[4];
    const float* kw  = (const float*)d_in[5];
    const float* kb  = (const float*)d_in[6];
    const float* ks  = (const float*)d_in[7];
    const float* kt  = (const float*)d_in[8];
    const float* vw  = (const float*)d_in[9];
    const float* vb  = (const float*)d_in[10];
    const float* vs  = (const float*)d_in[11];
    const float* vt  = (const float*)d_in[12];
    const float* pw  = (const float*)d_in[13];
    const float* pb  = (const float*)d_in[14];
    const float* ps  = (const float*)d_in[15];
    const float* pt  = (const float*)d_in[16];
    const float* f1w = (const float*)d_in[17];
    const float* f1b = (const float*)d_in[18];
    const float* f1s = (const float*)d_in[19];
    const float* f1t = (const float*)d_in[20];
    const float* f2w = (const float*)d_in[21];
    const float* f2b = (const float*)d_in[22];
    const float* f2s = (const float*)d_in[23];
    const float* f2t = (const float*)d_in[24];

    float *obuf, *x1b, *qkvp;
    fp16 *xs, *ws, *spkf, *aspk, *hspk, *x1s;
    cudaGetSymbolAddress((void**)&xs,   g_xs);
    cudaGetSymbolAddress((void**)&ws,   g_ws);
    cudaGetSymbolAddress((void**)&spkf, g_spkf);
    cudaGetSymbolAddress((void**)&aspk, g_aspk);
    cudaGetSymbolAddress((void**)&hspk, g_hspk);
    cudaGetSymbolAddress((void**)&x1s,  g_x1s);
    cudaGetSymbolAddress((void**)&obuf, g_obuf);
    cudaGetSymbolAddress((void**)&x1b,  g_x1);
    cudaGetSymbolAddress((void**)&qkvp, g_qkvp);

    const int SZ_A2 = 1024 + 3 * 4 * 16384;   // 197632 (NA=2, NSTG=3)
    const int SZ_A1 = 1024 + 4 * 3 * 16384;   // 197632 (NA=1, NSTG=4)
    cudaFuncSetAttribute((gemm_lif<2, 3, 0>), cudaFuncAttributeMaxDynamicSharedMemorySize, SZ_A2);
    cudaFuncSetAttribute((gemm_lif<1, 4, 1>), cudaFuncAttributeMaxDynamicSharedMemorySize, SZ_A1);
    cudaFuncSetAttribute((gemm_lif<1, 4, 2>), cudaFuncAttributeMaxDynamicSharedMemorySize, SZ_A1);

    // splits
    {
        size_t n2 = MC / 2;
        split2_kernel<<<(int)((n2 + 255) / 256), 256>>>((const float2*)x,
            (__half2*)xs, (__half2*)(xs + MC), n2);
    }
    const float* wsrc[6] = {qw, kw, vw, pw, f1w, f2w};
    const size_t woff[6] = {WOFF_Q, WOFF_Q + (size_t)C_ * C_, WOFF_Q + 2 * (size_t)C_ * C_,
                            WOFF_P, WOFF_F1, WOFF_F2};
    const size_t wcnt[6] = {(size_t)C_ * C_, (size_t)C_ * C_, (size_t)C_ * C_,
                            (size_t)C_ * C_, (size_t)C_ * HD_, (size_t)C_ * HD_};
    for (int wI = 0; wI < 6; wI++) {
        size_t n2 = wcnt[wI] / 2;
        split2_kernel<<<(int)((n2 + 255) / 256), 256>>>((const float2*)wsrc[wI],
            (__half2*)(ws + woff[wI]), (__half2*)(ws + WTOT + woff[wI]), n2);
    }
    concat3_kernel<<<(C3_ + 255) / 256, 256>>>(qb, kb, vb, qkvp);
    concat3_kernel<<<(C3_ + 255) / 256, 256>>>(qs, ks, vs, qkvp + C3_);
    concat3_kernel<<<(C3_ + 255) / 256, 256>>>(qt, kt, vt, qkvp + 2 * C3_);

    const int lifC = (int)((PLANE_C / 2 + 255) / 256);
    const dim3 gQKV(C3_ / 128, BN_TOK / 128);   // (18, 64)
    const dim3 gC(C_ / 128, BN_TOK / 128);      // (6, 64)
    const dim3 gH(HD_ / 128, BN_TOK / 128);     // (24, 64)

    // fused qkv GEMM + BN + LIF -> fp16 spikes
    gemm_lif<2, 3, 0><<<gQKV, 256, SZ_A2>>>(
        xs, xs + MC, ws + WOFF_Q, ws + WTOT + WOFF_Q,
        qkvp, qkvp + C3_, qkvp + 2 * C3_, nullptr, nullptr, spkf, nullptr, C3_, C_);

    // attention + attn_lif
    attn_kernel<<<dim3(NW_, B_, T_), 128>>>(spkf, obuf);
    lif_spk_kernel<<<lifC, 256>>>((const float2*)obuf, (__half2*)aspk, PLANE_C / 2, 0.5f);

    // proj + BN + LIF + residual -> x1 (f32) + x1 splits (fp16)
    gemm_lif<1, 4, 1><<<gC, 256, SZ_A1>>>(
        aspk, aspk, ws + WOFF_P, ws + WTOT + WOFF_P,
        pb, ps, pt, x, x1b, x1s, x1s + MC, C_, C_);

    // f1 + BN + LIF -> h spikes
    gemm_lif<2, 3, 0><<<gH, 256, SZ_A2>>>(
        x1s, x1s + MC, ws + WOFF_F1, ws + WTOT + WOFF_F1,
        f1b, f1s, f1t, nullptr, nullptr, hspk, nullptr, HD_, C_);

    // f2 + BN + LIF + residual -> d_out
    gemm_lif<1, 4, 2><<<gC, 256, SZ_A1>>>(
        hspk, hspk, ws + WOFF_F2, ws + WTOT + WOFF_F2,
        f2b, f2s, f2t, x1b, (float*)d_out, nullptr, nullptr, C_, HD_);
}